// round 2
// baseline (speedup 1.0000x reference)
#include <cuda_runtime.h>
#include <cstddef>

#define NN   16384   // nodes
#define F_IN 512     // input feature dim
#define H    256     // hidden dim
#define MAXE 524288  // edges

// ---------------- device scratch (no allocations allowed) ----------------
__device__ float g_support[(size_t)NN * H];   // x @ gc_W
__device__ float g_H1[(size_t)NN * H];        // relu(agg)
__device__ int   g_cnt[NN];
__device__ int   g_rowptr[NN + 1];
__device__ int   g_cursor[NN];
__device__ int   g_ccol[MAXE];
__device__ float g_cw[MAXE];

// ---------------- small utility kernels ----------------
__global__ void zero_int_kernel(int* p, int n) {
    int i = blockIdx.x * blockDim.x + threadIdx.x;
    if (i < n) p[i] = 0;
}

__global__ void count_edges_kernel(const int* __restrict__ erow, int E, int* __restrict__ cnt) {
    int e = blockIdx.x * blockDim.x + threadIdx.x;
    if (e < E) atomicAdd(&cnt[erow[e]], 1);
}

// exclusive scan of 16384 ints in a single 1024-thread block (16 per thread)
__global__ void scan_kernel(const int* __restrict__ cnt, int* __restrict__ rowptr,
                            int* __restrict__ cursor) {
    __shared__ int partials[1024];
    int t = threadIdx.x;
    int sum = 0;
#pragma unroll
    for (int i = 0; i < 16; i++) sum += cnt[t * 16 + i];
    partials[t] = sum;
    __syncthreads();
    // Hillis-Steele inclusive scan over 1024 partials
    for (int off = 1; off < 1024; off <<= 1) {
        int add = 0;
        if (t >= off) add = partials[t - off];
        __syncthreads();
        partials[t] += add;
        __syncthreads();
    }
    int run = (t == 0) ? 0 : partials[t - 1];
#pragma unroll
    for (int i = 0; i < 16; i++) {
        int c = cnt[t * 16 + i];
        rowptr[t * 16 + i] = run;
        cursor[t * 16 + i] = run;
        run += c;
    }
    if (t == 1023) rowptr[NN] = run;
}

__global__ void fill_csr_kernel(const int* __restrict__ erow, const int* __restrict__ ecol,
                                const float* __restrict__ ew, int E,
                                int* __restrict__ cursor, int* __restrict__ ccol,
                                float* __restrict__ cw) {
    int e = blockIdx.x * blockDim.x + threadIdx.x;
    if (e < E) {
        int r = erow[e];
        int p = atomicAdd(&cursor[r], 1);
        ccol[p] = ecol[e];
        cw[p]   = ew[e];
    }
}

// one block per row; thread t owns feature dim t. support is L2-resident (16.8MB).
__global__ __launch_bounds__(256) void gather_relu_kernel(
    const float* __restrict__ support, const int* __restrict__ ccol,
    const float* __restrict__ cw, const int* __restrict__ rowptr,
    float* __restrict__ H1) {
    int r = blockIdx.x;
    int t = threadIdx.x;
    int beg = rowptr[r], end = rowptr[r + 1];
    __shared__ int   scol[128];
    __shared__ float sw[128];
    float acc = 0.f;
    for (int base = beg; base < end; base += 128) {
        int n = end - base; if (n > 128) n = 128;
        if (t < n) { scol[t] = ccol[base + t]; sw[t] = cw[base + t]; }
        __syncthreads();
        for (int j = 0; j < n; j++)
            acc += sw[j] * support[(size_t)scol[j] * H + t];
        __syncthreads();
    }
    H1[(size_t)r * H + t] = fmaxf(acc, 0.f);
}

// ---------------- tiled fp32 GEMM: 128x128 block, 8x8 per thread ----------------
// C[M,N] = A[M,K] * op(B) (+ bias[n])
// TRANSB=false: B is [K,N] row-major (C = A @ B)
// TRANSB=true : B is [N,K] row-major (C = A @ B^T)
// Requires M%128==0, N%128==0, K%8==0.
template <bool TRANSB>
__global__ __launch_bounds__(256) void gemm_tile128_kernel(
    const float* __restrict__ A, const float* __restrict__ B,
    const float* __restrict__ bias, float* __restrict__ C,
    int M, int N, int K) {
    __shared__ float As[8][132];
    __shared__ float Bs[8][132];

    const int tid = threadIdx.x;
    const int tx = tid & 15;   // n-direction (0..15)
    const int ty = tid >> 4;   // m-direction (0..15)
    const int bn0 = blockIdx.x * 128;
    const int bm0 = blockIdx.y * 128;

    // A (and B if TRANSB) staging: thread -> (row = tid/2, k4 = (tid&1)*4)
    const int s_row = tid >> 1;
    const int s_k4  = (tid & 1) << 2;

    const float* Ap = A + (size_t)(bm0 + s_row) * K + s_k4;
    const float* Bp_t = TRANSB ? (B + (size_t)(bn0 + s_row) * K + s_k4) : nullptr;

    float acc[8][8];
#pragma unroll
    for (int i = 0; i < 8; i++)
#pragma unroll
        for (int j = 0; j < 8; j++) acc[i][j] = 0.f;

    for (int kt = 0; kt < K; kt += 8) {
        float4 av = *(const float4*)(Ap + kt);
        As[s_k4 + 0][s_row] = av.x;
        As[s_k4 + 1][s_row] = av.y;
        As[s_k4 + 2][s_row] = av.z;
        As[s_k4 + 3][s_row] = av.w;
        if (TRANSB) {
            float4 bv = *(const float4*)(Bp_t + kt);
            Bs[s_k4 + 0][s_row] = bv.x;
            Bs[s_k4 + 1][s_row] = bv.y;
            Bs[s_k4 + 2][s_row] = bv.z;
            Bs[s_k4 + 3][s_row] = bv.w;
        } else {
            int bk  = tid >> 5;          // 0..7
            int bn4 = (tid & 31) << 2;   // 0..124
            float4 bv = *(const float4*)(B + (size_t)(kt + bk) * N + bn0 + bn4);
            *(float4*)&Bs[bk][bn4] = bv;
        }
        __syncthreads();
#pragma unroll
        for (int k = 0; k < 8; k++) {
            float4 a01 = *(const float4*)&As[k][ty * 8];
            float4 a23 = *(const float4*)&As[k][ty * 8 + 4];
            float4 b01 = *(const float4*)&Bs[k][tx * 8];
            float4 b23 = *(const float4*)&Bs[k][tx * 8 + 4];
            float af[8] = {a01.x, a01.y, a01.z, a01.w, a23.x, a23.y, a23.z, a23.w};
            float bf[8] = {b01.x, b01.y, b01.z, b01.w, b23.x, b23.y, b23.z, b23.w};
#pragma unroll
            for (int i = 0; i < 8; i++)
#pragma unroll
                for (int j = 0; j < 8; j++) acc[i][j] += af[i] * bf[j];
        }
        __syncthreads();
    }

    float bvals[8];
#pragma unroll
    for (int j = 0; j < 8; j++)
        bvals[j] = bias ? bias[bn0 + tx * 8 + j] : 0.f;

#pragma unroll
    for (int i = 0; i < 8; i++) {
        size_t row = (size_t)(bm0 + ty * 8 + i);
        float* Cp = C + row * (size_t)N + bn0 + tx * 8;
#pragma unroll
        for (int j = 0; j < 8; j += 4) {
            float4 v;
            v.x = acc[i][j + 0] + bvals[j + 0];
            v.y = acc[i][j + 1] + bvals[j + 1];
            v.z = acc[i][j + 2] + bvals[j + 2];
            v.w = acc[i][j + 3] + bvals[j + 3];
            *(float4*)(Cp + j) = v;
        }
    }
}

// ---------------- launch ----------------
extern "C" void kernel_launch(void* const* d_in, const int* in_sizes, int n_in,
                              void* d_out, int out_size) {
    const float* x      = (const float*)d_in[0];
    const int*   erow   = (const int*)d_in[1];
    const int*   ecol   = (const int*)d_in[2];
    const float* ew     = (const float*)d_in[3];
    const float* gcW    = (const float*)d_in[4];
    const float* nodeW  = (const float*)d_in[5];
    const float* nodeb  = (const float*)d_in[6];
    const float* neighW = (const float*)d_in[7];
    const float* neighb = (const float*)d_in[8];

    float* out       = (float*)d_out;
    float* adj       = out;                                  // [NN, NN]
    float* node_emb  = out + (size_t)NN * NN;                // [NN, H]
    float* neigh_emb = node_emb + (size_t)NN * H;            // [NN, H]

    const int E = in_sizes[1];

    float *support, *H1, *cw;
    int *cnt, *rowptr, *cursor, *ccol;
    cudaGetSymbolAddress((void**)&support, g_support);
    cudaGetSymbolAddress((void**)&H1,      g_H1);
    cudaGetSymbolAddress((void**)&cnt,     g_cnt);
    cudaGetSymbolAddress((void**)&rowptr,  g_rowptr);
    cudaGetSymbolAddress((void**)&cursor,  g_cursor);
    cudaGetSymbolAddress((void**)&ccol,    g_ccol);
    cudaGetSymbolAddress((void**)&cw,      g_cw);

    // 1) CSR build
    zero_int_kernel<<<(NN + 255) / 256, 256>>>(cnt, NN);
    count_edges_kernel<<<(E + 255) / 256, 256>>>(erow, E, cnt);
    scan_kernel<<<1, 1024>>>(cnt, rowptr, cursor);
    fill_csr_kernel<<<(E + 255) / 256, 256>>>(erow, ecol, ew, E, cursor, ccol, cw);

    // 2) support = x @ gc_W   [NN,512]x[512,256]
    gemm_tile128_kernel<false><<<dim3(H / 128, NN / 128), 256>>>(
        x, gcW, nullptr, support, NN, H, F_IN);

    // 3) H1 = relu(segment_sum(w * support[col]))
    gather_relu_kernel<<<NN, 256>>>(support, ccol, cw, rowptr, H1);

    // 4) node_emb = H1 @ node_W^T + node_b ; neigh_emb = H1 @ neigh_W^T + neigh_b
    gemm_tile128_kernel<true><<<dim3(H / 128, NN / 128), 256>>>(
        H1, nodeW, nodeb, node_emb, NN, H, H);
    gemm_tile128_kernel<true><<<dim3(H / 128, NN / 128), 256>>>(
        H1, neighW, neighb, neigh_emb, NN, H, H);

    // 5) adj = node_emb @ neigh_emb^T   [NN,256]x[256,NN]  (137 GFLOP)
    gemm_tile128_kernel<true><<<dim3(NN / 128, NN / 128), 256>>>(
        node_emb, neigh_emb, nullptr, adj, NN, NN, H);
}

// round 4
// speedup vs baseline: 2.2343x; 2.2343x over previous
#include <cuda_runtime.h>
#include <cuda_bf16.h>
#include <cstdint>
#include <cstddef>

#define NN   16384   // nodes
#define F_IN 512     // input feature dim
#define H    256     // hidden dim
#define MAXE 524288  // edges
#define KP   768     // bf16x3 expanded K (3*H)

// ---------------- device scratch (no allocations allowed) ----------------
__device__ float g_support[(size_t)NN * H];
__device__ float g_H1[(size_t)NN * H];
__device__ int   g_cnt[NN];
__device__ int   g_rowptr[NN + 1];
__device__ int   g_cursor[NN];
__device__ int   g_ccol[MAXE];
__device__ float g_cw[MAXE];
__device__ __nv_bfloat16 g_Abf[(size_t)NN * KP];   // [Ahi | Ahi | Alo]
__device__ __nv_bfloat16 g_Bbf[(size_t)NN * KP];   // [Bhi | Blo | Bhi]

// ---------------- PTX helpers ----------------
__device__ __forceinline__ uint32_t smem_u32(const void* p) {
    uint32_t a;
    asm("{ .reg .u64 t; cvta.to.shared.u64 t, %1; cvt.u32.u64 %0, t; }" : "=r"(a) : "l"(p));
    return a;
}
#define CP_ASYNC16(sm, gp) asm volatile("cp.async.cg.shared.global [%0], [%1], 16;" :: "r"(sm), "l"(gp))
#define CP_COMMIT()        asm volatile("cp.async.commit_group;" ::: "memory")
#define CP_WAIT1()         asm volatile("cp.async.wait_group 1;" ::: "memory")
#define CP_WAIT0()         asm volatile("cp.async.wait_group 0;" ::: "memory")

__device__ __forceinline__ uint32_t sw128(uint32_t off) {
    return off ^ ((off >> 3) & 0x70);
}

__device__ __forceinline__ void ldsm_x4(uint32_t& r0, uint32_t& r1, uint32_t& r2, uint32_t& r3,
                                        uint32_t addr) {
    asm volatile("ldmatrix.sync.aligned.m8n8.x4.shared.b16 {%0,%1,%2,%3}, [%4];"
                 : "=r"(r0), "=r"(r1), "=r"(r2), "=r"(r3) : "r"(addr));
}
__device__ __forceinline__ void mma_bf16(float& c0, float& c1, float& c2, float& c3,
                                         uint32_t a0, uint32_t a1, uint32_t a2, uint32_t a3,
                                         uint32_t b0, uint32_t b1) {
    asm volatile("mma.sync.aligned.m16n8k16.row.col.f32.bf16.bf16.f32 "
                 "{%0,%1,%2,%3}, {%4,%5,%6,%7}, {%8,%9}, {%0,%1,%2,%3};"
                 : "+f"(c0), "+f"(c1), "+f"(c2), "+f"(c3)
                 : "r"(a0), "r"(a1), "r"(a2), "r"(a3), "r"(b0), "r"(b1));
}

// ---------------- small utility kernels ----------------
__global__ void zero_int_kernel(int* p, int n) {
    int i = blockIdx.x * blockDim.x + threadIdx.x;
    if (i < n) p[i] = 0;
}
__global__ void count_edges_kernel(const int* __restrict__ erow, int E, int* __restrict__ cnt) {
    int e = blockIdx.x * blockDim.x + threadIdx.x;
    if (e < E) atomicAdd(&cnt[erow[e]], 1);
}
__global__ void scan_kernel(const int* __restrict__ cnt, int* __restrict__ rowptr,
                            int* __restrict__ cursor) {
    __shared__ int partials[1024];
    int t = threadIdx.x;
    int sum = 0;
#pragma unroll
    for (int i = 0; i < 16; i++) sum += cnt[t * 16 + i];
    partials[t] = sum;
    __syncthreads();
    for (int off = 1; off < 1024; off <<= 1) {
        int add = 0;
        if (t >= off) add = partials[t - off];
        __syncthreads();
        partials[t] += add;
        __syncthreads();
    }
    int run = (t == 0) ? 0 : partials[t - 1];
#pragma unroll
    for (int i = 0; i < 16; i++) {
        int c = cnt[t * 16 + i];
        rowptr[t * 16 + i] = run;
        cursor[t * 16 + i] = run;
        run += c;
    }
    if (t == 1023) rowptr[NN] = run;
}
__global__ void fill_csr_kernel(const int* __restrict__ erow, const int* __restrict__ ecol,
                                const float* __restrict__ ew, int E,
                                int* __restrict__ cursor, int* __restrict__ ccol,
                                float* __restrict__ cw) {
    int e = blockIdx.x * blockDim.x + threadIdx.x;
    if (e < E) {
        int r = erow[e];
        int p = atomicAdd(&cursor[r], 1);
        ccol[p] = ecol[e];
        cw[p]   = ew[e];
    }
}
__global__ __launch_bounds__(256) void gather_relu_kernel(
    const float* __restrict__ support, const int* __restrict__ ccol,
    const float* __restrict__ cw, const int* __restrict__ rowptr,
    float* __restrict__ H1) {
    int r = blockIdx.x;
    int t = threadIdx.x;
    int beg = rowptr[r], end = rowptr[r + 1];
    __shared__ int   scol[128];
    __shared__ float sw[128];
    float acc = 0.f;
    for (int base = beg; base < end; base += 128) {
        int n = end - base; if (n > 128) n = 128;
        if (t < n) { scol[t] = ccol[base + t]; sw[t] = cw[base + t]; }
        __syncthreads();
        for (int j = 0; j < n; j++)
            acc += sw[j] * support[(size_t)scol[j] * H + t];
        __syncthreads();
    }
    H1[(size_t)r * H + t] = fmaxf(acc, 0.f);
}

// split fp32 -> (hi, lo) bf16 pair, build expanded K=768 operands
__global__ void split_kernel(const float* __restrict__ ne, const float* __restrict__ me,
                             __nv_bfloat16* __restrict__ A2, __nv_bfloat16* __restrict__ B2) {
    int idx = blockIdx.x * blockDim.x + threadIdx.x;  // over NN*H
    int r = idx >> 8, k = idx & 255;
    size_t base = (size_t)r * KP;
    float a = ne[idx];
    __nv_bfloat16 ah = __float2bfloat16(a);
    __nv_bfloat16 al = __float2bfloat16(a - __bfloat162float(ah));
    A2[base + k] = ah; A2[base + 256 + k] = ah; A2[base + 512 + k] = al;
    float b = me[idx];
    __nv_bfloat16 bh = __float2bfloat16(b);
    __nv_bfloat16 bl = __float2bfloat16(b - __bfloat162float(bh));
    B2[base + k] = bh; B2[base + 256 + k] = bl; B2[base + 512 + k] = bh;
}

// ---------------- fp32 tiled GEMM (small GEMMs, full precision) ----------------
template <bool TRANSB>
__global__ __launch_bounds__(256) void gemm_tile128_kernel(
    const float* __restrict__ A, const float* __restrict__ B,
    const float* __restrict__ bias, float* __restrict__ C,
    int M, int N, int K) {
    __shared__ float As[8][132];
    __shared__ float Bs[8][132];
    const int tid = threadIdx.x;
    const int tx = tid & 15;
    const int ty = tid >> 4;
    const int bn0 = blockIdx.x * 128;
    const int bm0 = blockIdx.y * 128;
    const int s_row = tid >> 1;
    const int s_k4  = (tid & 1) << 2;
    const float* Ap = A + (size_t)(bm0 + s_row) * K + s_k4;
    const float* Bp_t = TRANSB ? (B + (size_t)(bn0 + s_row) * K + s_k4) : nullptr;
    float acc[8][8];
#pragma unroll
    for (int i = 0; i < 8; i++)
#pragma unroll
        for (int j = 0; j < 8; j++) acc[i][j] = 0.f;
    for (int kt = 0; kt < K; kt += 8) {
        float4 av = *(const float4*)(Ap + kt);
        As[s_k4 + 0][s_row] = av.x; As[s_k4 + 1][s_row] = av.y;
        As[s_k4 + 2][s_row] = av.z; As[s_k4 + 3][s_row] = av.w;
        if (TRANSB) {
            float4 bv = *(const float4*)(Bp_t + kt);
            Bs[s_k4 + 0][s_row] = bv.x; Bs[s_k4 + 1][s_row] = bv.y;
            Bs[s_k4 + 2][s_row] = bv.z; Bs[s_k4 + 3][s_row] = bv.w;
        } else {
            int bk  = tid >> 5;
            int bn4 = (tid & 31) << 2;
            float4 bv = *(const float4*)(B + (size_t)(kt + bk) * N + bn0 + bn4);
            *(float4*)&Bs[bk][bn4] = bv;
        }
        __syncthreads();
#pragma unroll
        for (int k = 0; k < 8; k++) {
            float4 a01 = *(const float4*)&As[k][ty * 8];
            float4 a23 = *(const float4*)&As[k][ty * 8 + 4];
            float4 b01 = *(const float4*)&Bs[k][tx * 8];
            float4 b23 = *(const float4*)&Bs[k][tx * 8 + 4];
            float af[8] = {a01.x, a01.y, a01.z, a01.w, a23.x, a23.y, a23.z, a23.w};
            float bf[8] = {b01.x, b01.y, b01.z, b01.w, b23.x, b23.y, b23.z, b23.w};
#pragma unroll
            for (int i = 0; i < 8; i++)
#pragma unroll
                for (int j = 0; j < 8; j++) acc[i][j] += af[i] * bf[j];
        }
        __syncthreads();
    }
    float bvals[8];
#pragma unroll
    for (int j = 0; j < 8; j++) bvals[j] = bias ? bias[bn0 + tx * 8 + j] : 0.f;
#pragma unroll
    for (int i = 0; i < 8; i++) {
        size_t row = (size_t)(bm0 + ty * 8 + i);
        float* Cp = C + row * (size_t)N + bn0 + tx * 8;
#pragma unroll
        for (int j = 0; j < 8; j += 4) {
            float4 v;
            v.x = acc[i][j + 0] + bvals[j + 0];
            v.y = acc[i][j + 1] + bvals[j + 1];
            v.z = acc[i][j + 2] + bvals[j + 2];
            v.w = acc[i][j + 3] + bvals[j + 3];
            *(float4*)(Cp + j) = v;
        }
    }
}

// ---------------- HMMA bf16 GEMM: C[16384,16384] = A'[16384,768] @ B'[16384,768]^T ----
// CTA 128x128, BK=64 bf16 (128B rows, SW128), 3-stage cp.async,
// 8 warps (2 M x 4 N), warp tile 64x32, mma.m16n8k16 bf16 fp32-accum.
#define NCHUNK   12          // 768 / 64
#define STAGE_SZ 32768u      // A 16KB + B 16KB
#define ADJ_SMEM (3 * 32768) // 96KB; epilogue (128x132 f32 = 67.6KB) aliases

__device__ __forceinline__ void load_stage(const char* __restrict__ Ab,
                                           const char* __restrict__ Bb,
                                           uint32_t stA, uint32_t stB,
                                           int bm0, int bn0, int kt, int tid) {
    int s  = tid & 7;        // 16B segment (8 per 128B row)
    int r0 = tid >> 3;       // 0..31
#pragma unroll
    for (int rr = 0; rr < 128; rr += 32) {
        int r = r0 + rr;
        uint32_t soff = sw128((uint32_t)(r * 128 + s * 16));
        size_t gA = ((size_t)(bm0 + r) * KP + kt * 64) * 2 + s * 16;
        size_t gB = ((size_t)(bn0 + r) * KP + kt * 64) * 2 + s * 16;
        CP_ASYNC16(stA + soff, Ab + gA);
        CP_ASYNC16(stB + soff, Bb + gB);
    }
}

__global__ __launch_bounds__(256, 2)
void adj_gemm_hmma_kernel(const __nv_bfloat16* __restrict__ A,
                          const __nv_bfloat16* __restrict__ B,
                          float* __restrict__ C) {
    extern __shared__ char smem[];
    uint32_t sb = smem_u32(smem);
    const int tid = threadIdx.x;
    const int wid = tid >> 5, lid = tid & 31;
    const int warp_m = wid >> 2;        // 0..1 -> M offset *64
    const int warp_n = wid & 3;         // 0..3 -> N offset *32
    const int bn0 = blockIdx.x * 128;
    const int bm0 = blockIdx.y * 128;
    const char* Ab = (const char*)A;
    const char* Bb = (const char*)B;

    float acc[4][4][4];                 // [im][in8][quad]
#pragma unroll
    for (int i = 0; i < 4; i++)
#pragma unroll
        for (int j = 0; j < 4; j++)
#pragma unroll
            for (int q = 0; q < 4; q++) acc[i][j][q] = 0.f;

    // prologue: stages 0, 1
    load_stage(Ab, Bb, sb, sb + 16384u, bm0, bn0, 0, tid);
    CP_COMMIT();
    load_stage(Ab, Bb, sb + STAGE_SZ, sb + STAGE_SZ + 16384u, bm0, bn0, 1, tid);
    CP_COMMIT();

    // precomputed lane pieces for ldmatrix addressing
    const int a_row   = (lid & 15);           // row within m16
    const int a_chunk = (lid >> 4);           // 0/1 -> k halves
    const int b_nin   = (lid & 7) + ((lid >> 4) << 3);  // n within n16
    const int b_chunk = (lid >> 3) & 1;

    for (int i = 0; i < NCHUNK; i++) {
        if (i < NCHUNK - 1) CP_WAIT1(); else CP_WAIT0();
        __syncthreads();
        uint32_t stA = sb + (uint32_t)(i % 3) * STAGE_SZ;
        uint32_t stB = stA + 16384u;

#pragma unroll
        for (int kk = 0; kk < 4; kk++) {   // four k16 steps in BK=64
            uint32_t af[4][4];
#pragma unroll
            for (int im = 0; im < 4; im++) {
                uint32_t off = (uint32_t)((warp_m * 64 + im * 16 + a_row) * 128
                                          + kk * 32 + a_chunk * 16);
                ldsm_x4(af[im][0], af[im][1], af[im][2], af[im][3], stA + sw128(off));
            }
            uint32_t bf[4][2];
#pragma unroll
            for (int bt = 0; bt < 2; bt++) {
                uint32_t off = (uint32_t)((warp_n * 32 + bt * 16 + b_nin) * 128
                                          + kk * 32 + b_chunk * 16);
                uint32_t r0, r1, r2, r3;
                ldsm_x4(r0, r1, r2, r3, stB + sw128(off));
                bf[bt * 2 + 0][0] = r0; bf[bt * 2 + 0][1] = r1;
                bf[bt * 2 + 1][0] = r2; bf[bt * 2 + 1][1] = r3;
            }
#pragma unroll
            for (int im = 0; im < 4; im++)
#pragma unroll
                for (int in = 0; in < 4; in++)
                    mma_bf16(acc[im][in][0], acc[im][in][1], acc[im][in][2], acc[im][in][3],
                             af[im][0], af[im][1], af[im][2], af[im][3],
                             bf[in][0], bf[in][1]);
        }

        if (i + 2 < NCHUNK) {
            uint32_t nstA = sb + (uint32_t)((i + 2) % 3) * STAGE_SZ;
            load_stage(Ab, Bb, nstA, nstA + 16384u, bm0, bn0, i + 2, tid);
            CP_COMMIT();
        }
    }

    // ---------------- epilogue: stage through smem for coalesced stores ----------------
    __syncthreads();
    float* Cs = (float*)smem;           // [128][132]
    const int qrow = lid >> 2;          // l/4
    const int qcol = (lid & 3) * 2;
#pragma unroll
    for (int im = 0; im < 4; im++) {
#pragma unroll
        for (int in = 0; in < 4; in++) {
            int row = warp_m * 64 + im * 16 + qrow;
            int col = warp_n * 32 + in * 8 + qcol;
            *(float2*)&Cs[row * 132 + col]        = make_float2(acc[im][in][0], acc[im][in][1]);
            *(float2*)&Cs[(row + 8) * 132 + col]  = make_float2(acc[im][in][2], acc[im][in][3]);
        }
    }
    __syncthreads();
    {
        int row = tid >> 1;
        int c0  = (tid & 1) * 64;
        float* dst = C + (size_t)(bm0 + row) * NN + bn0 + c0;
        const float* src = &Cs[row * 132 + c0];
#pragma unroll
        for (int j = 0; j < 16; j++)
            *(float4*)(dst + j * 4) = *(const float4*)(src + j * 4);
    }
}

// ---------------- launch ----------------
extern "C" void kernel_launch(void* const* d_in, const int* in_sizes, int n_in,
                              void* d_out, int out_size) {
    const float* x      = (const float*)d_in[0];
    const int*   erow   = (const int*)d_in[1];
    const int*   ecol   = (const int*)d_in[2];
    const float* ew     = (const float*)d_in[3];
    const float* gcW    = (const float*)d_in[4];
    const float* nodeW  = (const float*)d_in[5];
    const float* nodeb  = (const float*)d_in[6];
    const float* neighW = (const float*)d_in[7];
    const float* neighb = (const float*)d_in[8];

    float* out       = (float*)d_out;
    float* adj       = out;
    float* node_emb  = out + (size_t)NN * NN;
    float* neigh_emb = node_emb + (size_t)NN * H;

    const int E = in_sizes[1];

    float *support, *H1, *cw;
    int *cnt, *rowptr, *cursor, *ccol;
    __nv_bfloat16 *A2, *B2;
    cudaGetSymbolAddress((void**)&support, g_support);
    cudaGetSymbolAddress((void**)&H1,      g_H1);
    cudaGetSymbolAddress((void**)&cnt,     g_cnt);
    cudaGetSymbolAddress((void**)&rowptr,  g_rowptr);
    cudaGetSymbolAddress((void**)&cursor,  g_cursor);
    cudaGetSymbolAddress((void**)&ccol,    g_ccol);
    cudaGetSymbolAddress((void**)&cw,      g_cw);
    cudaGetSymbolAddress((void**)&A2,      g_Abf);
    cudaGetSymbolAddress((void**)&B2,      g_Bbf);

    static bool attr_set = false;
    if (!attr_set) {
        cudaFuncSetAttribute(adj_gemm_hmma_kernel,
                             cudaFuncAttributeMaxDynamicSharedMemorySize, ADJ_SMEM);
        attr_set = true;
    }

    // 1) CSR build
    zero_int_kernel<<<(NN + 255) / 256, 256>>>(cnt, NN);
    count_edges_kernel<<<(E + 255) / 256, 256>>>(erow, E, cnt);
    scan_kernel<<<1, 1024>>>(cnt, rowptr, cursor);
    fill_csr_kernel<<<(E + 255) / 256, 256>>>(erow, ecol, ew, E, cursor, ccol, cw);

    // 2) support = x @ gc_W
    gemm_tile128_kernel<false><<<dim3(H / 128, NN / 128), 256>>>(
        x, gcW, nullptr, support, NN, H, F_IN);

    // 3) H1 = relu(segment_sum(w * support[col]))
    gather_relu_kernel<<<NN, 256>>>(support, ccol, cw, rowptr, H1);

    // 4) linear projections (fp32, exact)
    gemm_tile128_kernel<true><<<dim3(H / 128, NN / 128), 256>>>(
        H1, nodeW, nodeb, node_emb, NN, H, H);
    gemm_tile128_kernel<true><<<dim3(H / 128, NN / 128), 256>>>(
        H1, neighW, neighb, neigh_emb, NN, H, H);

    // 5) bf16x3 split + HMMA GEMM for adj
    split_kernel<<<(NN * H) / 256, 256>>>(node_emb, neigh_emb, A2, B2);
    adj_gemm_hmma_kernel<<<dim3(NN / 128, NN / 128), 256, ADJ_SMEM>>>(A2, B2, adj);
}

// round 5
// speedup vs baseline: 2.2877x; 1.0239x over previous
#include <cuda_runtime.h>
#include <cuda_bf16.h>
#include <cstdint>
#include <cstddef>

#define NN   16384   // nodes
#define F_IN 512     // input feature dim
#define H    256     // hidden dim
#define MAXE 524288  // edges
#define KP3  768     // 3*H
#define KPX  1536    // 3*F_IN

// ---------------- device scratch (no allocations allowed) ----------------
__device__ float g_support[(size_t)NN * H];
__device__ float g_H1[(size_t)NN * H];
__device__ int   g_cnt[NN];
__device__ int   g_rowptr[NN + 1];
__device__ int   g_cursor[NN];
__device__ int   g_ccol[MAXE];
__device__ float g_cw[MAXE];
__device__ __nv_bfloat16 g_xs[(size_t)NN * KPX];    // x split (A-pattern)
__device__ __nv_bfloat16 g_gcWs[(size_t)H * KPX];   // gc_W split+transposed (B-pattern)
__device__ __nv_bfloat16 g_H1s[(size_t)NN * KP3];   // H1 split (A-pattern)
__device__ __nv_bfloat16 g_nWs[(size_t)H * KP3];    // node_W split (B-pattern)
__device__ __nv_bfloat16 g_gWs[(size_t)H * KP3];    // neigh_W split (B-pattern)
__device__ __nv_bfloat16 g_Abf[(size_t)NN * KP3];   // node_emb split (A-pattern)
__device__ __nv_bfloat16 g_Bbf[(size_t)NN * KP3];   // neigh_emb split (B-pattern)

// ---------------- PTX helpers ----------------
__device__ __forceinline__ uint32_t smem_u32(const void* p) {
    uint32_t a;
    asm("{ .reg .u64 t; cvta.to.shared.u64 t, %1; cvt.u32.u64 %0, t; }" : "=r"(a) : "l"(p));
    return a;
}
#define CP_ASYNC16(sm, gp) asm volatile("cp.async.cg.shared.global [%0], [%1], 16;" :: "r"(sm), "l"(gp))
#define CP_COMMIT()        asm volatile("cp.async.commit_group;" ::: "memory")
#define CP_WAIT1()         asm volatile("cp.async.wait_group 1;" ::: "memory")
#define CP_WAIT0()         asm volatile("cp.async.wait_group 0;" ::: "memory")

__device__ __forceinline__ uint32_t sw128(uint32_t off) {
    return off ^ ((off >> 3) & 0x70);
}
__device__ __forceinline__ void ldsm_x4(uint32_t& r0, uint32_t& r1, uint32_t& r2, uint32_t& r3,
                                        uint32_t addr) {
    asm volatile("ldmatrix.sync.aligned.m8n8.x4.shared.b16 {%0,%1,%2,%3}, [%4];"
                 : "=r"(r0), "=r"(r1), "=r"(r2), "=r"(r3) : "r"(addr));
}
__device__ __forceinline__ void mma_bf16(float& c0, float& c1, float& c2, float& c3,
                                         uint32_t a0, uint32_t a1, uint32_t a2, uint32_t a3,
                                         uint32_t b0, uint32_t b1) {
    asm volatile("mma.sync.aligned.m16n8k16.row.col.f32.bf16.bf16.f32 "
                 "{%0,%1,%2,%3}, {%4,%5,%6,%7}, {%8,%9}, {%0,%1,%2,%3};"
                 : "+f"(c0), "+f"(c1), "+f"(c2), "+f"(c3)
                 : "r"(a0), "r"(a1), "r"(a2), "r"(a3), "r"(b0), "r"(b1));
}

// ---------------- small utility kernels ----------------
__global__ void zero_int_kernel(int* p, int n) {
    int i = blockIdx.x * blockDim.x + threadIdx.x;
    if (i < n) p[i] = 0;
}
__global__ void count_edges_kernel(const int* __restrict__ erow, int E, int* __restrict__ cnt) {
    int e = blockIdx.x * blockDim.x + threadIdx.x;
    if (e < E) atomicAdd(&cnt[erow[e]], 1);
}
__global__ void scan_kernel(const int* __restrict__ cnt, int* __restrict__ rowptr,
                            int* __restrict__ cursor) {
    __shared__ int partials[1024];
    int t = threadIdx.x;
    int sum = 0;
#pragma unroll
    for (int i = 0; i < 16; i++) sum += cnt[t * 16 + i];
    partials[t] = sum;
    __syncthreads();
    for (int off = 1; off < 1024; off <<= 1) {
        int add = 0;
        if (t >= off) add = partials[t - off];
        __syncthreads();
        partials[t] += add;
        __syncthreads();
    }
    int run = (t == 0) ? 0 : partials[t - 1];
#pragma unroll
    for (int i = 0; i < 16; i++) {
        int c = cnt[t * 16 + i];
        rowptr[t * 16 + i] = run;
        cursor[t * 16 + i] = run;
        run += c;
    }
    if (t == 1023) rowptr[NN] = run;
}
__global__ void fill_csr_kernel(const int* __restrict__ erow, const int* __restrict__ ecol,
                                const float* __restrict__ ew, int E,
                                int* __restrict__ cursor, int* __restrict__ ccol,
                                float* __restrict__ cw) {
    int e = blockIdx.x * blockDim.x + threadIdx.x;
    if (e < E) {
        int r = erow[e];
        int p = atomicAdd(&cursor[r], 1);
        ccol[p] = ecol[e];
        cw[p]   = ew[e];
    }
}
__global__ __launch_bounds__(256) void gather_relu_kernel(
    const float* __restrict__ support, const int* __restrict__ ccol,
    const float* __restrict__ cw, const int* __restrict__ rowptr,
    float* __restrict__ H1) {
    int r = blockIdx.x;
    int t = threadIdx.x;
    int beg = rowptr[r], end = rowptr[r + 1];
    __shared__ int   scol[128];
    __shared__ float sw[128];
    float acc = 0.f;
    for (int base = beg; base < end; base += 128) {
        int n = end - base; if (n > 128) n = 128;
        if (t < n) { scol[t] = ccol[base + t]; sw[t] = cw[base + t]; }
        __syncthreads();
        for (int j = 0; j < n; j++)
            acc += sw[j] * support[(size_t)scol[j] * H + t];
        __syncthreads();
    }
    H1[(size_t)r * H + t] = fmaxf(acc, 0.f);
}

// fp32 -> bf16x3 split. bpat=0: A-pattern [hi|hi|lo]; bpat=1: B-pattern [hi|lo|hi]
__global__ void split3_kernel(const float* __restrict__ src, __nv_bfloat16* __restrict__ dst,
                              int K, int bpat, int total) {
    int idx = blockIdx.x * blockDim.x + threadIdx.x;
    if (idx >= total) return;
    int r = idx / K, k = idx - r * K;
    size_t base = (size_t)r * (3 * K);
    float v = src[idx];
    __nv_bfloat16 vh = __float2bfloat16(v);
    __nv_bfloat16 vl = __float2bfloat16(v - __bfloat162float(vh));
    dst[base + k] = vh;
    dst[base + K + k]     = bpat ? vl : vh;
    dst[base + 2 * K + k] = bpat ? vh : vl;
}

// W[K,N] row-major -> dst[N, 3K] B-pattern (transpose + split), for x @ gc_W
__global__ void split3T_kernel(const float* __restrict__ W, __nv_bfloat16* __restrict__ dst,
                               int K, int N, int total) {
    int idx = blockIdx.x * blockDim.x + threadIdx.x;
    if (idx >= total) return;
    int k = idx / N, n = idx - k * N;
    size_t base = (size_t)n * (3 * K);
    float v = W[idx];
    __nv_bfloat16 vh = __float2bfloat16(v);
    __nv_bfloat16 vl = __float2bfloat16(v - __bfloat162float(vh));
    dst[base + k] = vh;
    dst[base + K + k] = vl;
    dst[base + 2 * K + k] = vh;
}

// split both embeddings for adj GEMM
__global__ void split_emb_kernel(const float* __restrict__ ne, const float* __restrict__ me,
                                 __nv_bfloat16* __restrict__ A2, __nv_bfloat16* __restrict__ B2) {
    int idx = blockIdx.x * blockDim.x + threadIdx.x;  // over NN*H
    int r = idx >> 8, k = idx & 255;
    size_t base = (size_t)r * KP3;
    float a = ne[idx];
    __nv_bfloat16 ah = __float2bfloat16(a);
    __nv_bfloat16 al = __float2bfloat16(a - __bfloat162float(ah));
    A2[base + k] = ah; A2[base + 256 + k] = ah; A2[base + 512 + k] = al;
    float b = me[idx];
    __nv_bfloat16 bh = __float2bfloat16(b);
    __nv_bfloat16 bl = __float2bfloat16(b - __bfloat162float(bh));
    B2[base + k] = bh; B2[base + 256 + k] = bl; B2[base + 512 + k] = bh;
}

// ---------------- unified HMMA bf16 GEMM ----------------
// C[bm0+128, bn0+256] += A[M,Kp] @ B[N,Kp]^T (+bias), bf16 ops, fp32 accum.
// CTA tile 128x256, warp tile 64x64 (8 warps, 2M x 4N), BK=64, 3-stage cp.async.
#define STAGE_SZ 49152u        // A 16KB + B 32KB
#define GEMM_SMEM (3 * 49152)  // 144KB; epilogue Cs[128][264] (135KB) aliases

__device__ __forceinline__ void load_stage(const char* __restrict__ Ab,
                                           const char* __restrict__ Bb,
                                           uint32_t stA, uint32_t stB,
                                           int bm0, int bn0, int kt, int Kp, int tid) {
    int s  = tid & 7;
    int r0 = tid >> 3;
#pragma unroll
    for (int rr = 0; rr < 128; rr += 32) {
        int r = r0 + rr;
        uint32_t soff = sw128((uint32_t)(r * 128 + s * 16));
        size_t g = ((size_t)(bm0 + r) * Kp + kt * 64) * 2 + s * 16;
        CP_ASYNC16(stA + soff, Ab + g);
    }
#pragma unroll
    for (int rr = 0; rr < 256; rr += 32) {
        int r = r0 + rr;
        uint32_t soff = sw128((uint32_t)(r * 128 + s * 16));
        size_t g = ((size_t)(bn0 + r) * Kp + kt * 64) * 2 + s * 16;
        CP_ASYNC16(stB + soff, Bb + g);
    }
}

__global__ __launch_bounds__(256, 1)
void hmma_gemm_kernel(const __nv_bfloat16* __restrict__ A,
                      const __nv_bfloat16* __restrict__ B,
                      const float* __restrict__ bias,
                      float* __restrict__ C,
                      int Kp, int ldc) {
    extern __shared__ char smem[];
    uint32_t sb = smem_u32(smem);
    const int tid = threadIdx.x;
    const int wid = tid >> 5, lid = tid & 31;
    const int warp_m = wid >> 2;        // 0..1 -> M*64
    const int warp_n = wid & 3;         // 0..3 -> N*64
    const int bn0 = blockIdx.x * 256;
    const int bm0 = blockIdx.y * 128;
    const char* Ab = (const char*)A;
    const char* Bb = (const char*)B;
    const int nchunk = Kp >> 6;

    float acc[4][8][4];
#pragma unroll
    for (int i = 0; i < 4; i++)
#pragma unroll
        for (int j = 0; j < 8; j++)
#pragma unroll
            for (int q = 0; q < 4; q++) acc[i][j][q] = 0.f;

    load_stage(Ab, Bb, sb, sb + 16384u, bm0, bn0, 0, Kp, tid);
    CP_COMMIT();
    load_stage(Ab, Bb, sb + STAGE_SZ, sb + STAGE_SZ + 16384u, bm0, bn0, 1, Kp, tid);
    CP_COMMIT();

    const int a_row   = (lid & 15);
    const int a_chunk = (lid >> 4);
    const int b_nin   = (lid & 7) + ((lid >> 4) << 3);
    const int b_chunk = (lid >> 3) & 1;

    for (int i = 0; i < nchunk; i++) {
        if (i < nchunk - 1) CP_WAIT1(); else CP_WAIT0();
        __syncthreads();
        uint32_t stA = sb + (uint32_t)(i % 3) * STAGE_SZ;
        uint32_t stB = stA + 16384u;

#pragma unroll
        for (int kk = 0; kk < 4; kk++) {
            uint32_t af[4][4];
#pragma unroll
            for (int im = 0; im < 4; im++) {
                uint32_t off = (uint32_t)((warp_m * 64 + im * 16 + a_row) * 128
                                          + kk * 32 + a_chunk * 16);
                ldsm_x4(af[im][0], af[im][1], af[im][2], af[im][3], stA + sw128(off));
            }
            uint32_t bf[8][2];
#pragma unroll
            for (int bt = 0; bt < 4; bt++) {
                uint32_t off = (uint32_t)((warp_n * 64 + bt * 16 + b_nin) * 128
                                          + kk * 32 + b_chunk * 16);
                uint32_t r0, r1, r2, r3;
                ldsm_x4(r0, r1, r2, r3, stB + sw128(off));
                bf[bt * 2 + 0][0] = r0; bf[bt * 2 + 0][1] = r1;
                bf[bt * 2 + 1][0] = r2; bf[bt * 2 + 1][1] = r3;
            }
#pragma unroll
            for (int im = 0; im < 4; im++)
#pragma unroll
                for (int in = 0; in < 8; in++)
                    mma_bf16(acc[im][in][0], acc[im][in][1], acc[im][in][2], acc[im][in][3],
                             af[im][0], af[im][1], af[im][2], af[im][3],
                             bf[in][0], bf[in][1]);
        }

        if (i + 2 < nchunk) {
            uint32_t nstA = sb + (uint32_t)((i + 2) % 3) * STAGE_SZ;
            load_stage(Ab, Bb, nstA, nstA + 16384u, bm0, bn0, i + 2, Kp, tid);
            CP_COMMIT();
        }
    }

    // epilogue: stage through smem for coalesced 128B stores
    __syncthreads();
    float* Cs = (float*)smem;          // [128][264]
    const int qrow = lid >> 2;
    const int qcol = (lid & 3) * 2;
#pragma unroll
    for (int im = 0; im < 4; im++) {
#pragma unroll
        for (int in = 0; in < 8; in++) {
            int row = warp_m * 64 + im * 16 + qrow;
            int col = warp_n * 64 + in * 8 + qcol;
            *(float2*)&Cs[row * 264 + col]       = make_float2(acc[im][in][0], acc[im][in][1]);
            *(float2*)&Cs[(row + 8) * 264 + col] = make_float2(acc[im][in][2], acc[im][in][3]);
        }
    }
    __syncthreads();
    {
        int row = tid >> 1;
        int c0  = (tid & 1) * 128;
        float* dst = C + (size_t)(bm0 + row) * ldc + bn0 + c0;
        const float* src = &Cs[row * 264 + c0];
#pragma unroll
        for (int j = 0; j < 32; j++) {
            float4 v = *(const float4*)(src + j * 4);
            if (bias) {
                float4 bv = *(const float4*)(bias + bn0 + c0 + j * 4);
                v.x += bv.x; v.y += bv.y; v.z += bv.z; v.w += bv.w;
            }
            *(float4*)(dst + j * 4) = v;
        }
    }
}

// ---------------- launch ----------------
extern "C" void kernel_launch(void* const* d_in, const int* in_sizes, int n_in,
                              void* d_out, int out_size) {
    const float* x      = (const float*)d_in[0];
    const int*   erow   = (const int*)d_in[1];
    const int*   ecol   = (const int*)d_in[2];
    const float* ew     = (const float*)d_in[3];
    const float* gcW    = (const float*)d_in[4];
    const float* nodeW  = (const float*)d_in[5];
    const float* nodeb  = (const float*)d_in[6];
    const float* neighW = (const float*)d_in[7];
    const float* neighb = (const float*)d_in[8];

    float* out       = (float*)d_out;
    float* adj       = out;
    float* node_emb  = out + (size_t)NN * NN;
    float* neigh_emb = node_emb + (size_t)NN * H;

    const int E = in_sizes[1];

    float *support, *H1, *cw;
    int *cnt, *rowptr, *cursor, *ccol;
    __nv_bfloat16 *xs, *gcWs, *H1s, *nWs, *gWs, *A2, *B2;
    cudaGetSymbolAddress((void**)&support, g_support);
    cudaGetSymbolAddress((void**)&H1,      g_H1);
    cudaGetSymbolAddress((void**)&cnt,     g_cnt);
    cudaGetSymbolAddress((void**)&rowptr,  g_rowptr);
    cudaGetSymbolAddress((void**)&cursor,  g_cursor);
    cudaGetSymbolAddress((void**)&ccol,    g_ccol);
    cudaGetSymbolAddress((void**)&cw,      g_cw);
    cudaGetSymbolAddress((void**)&xs,      g_xs);
    cudaGetSymbolAddress((void**)&gcWs,    g_gcWs);
    cudaGetSymbolAddress((void**)&H1s,     g_H1s);
    cudaGetSymbolAddress((void**)&nWs,     g_nWs);
    cudaGetSymbolAddress((void**)&gWs,     g_gWs);
    cudaGetSymbolAddress((void**)&A2,      g_Abf);
    cudaGetSymbolAddress((void**)&B2,      g_Bbf);

    static bool attr_set = false;
    if (!attr_set) {
        cudaFuncSetAttribute(hmma_gemm_kernel,
                             cudaFuncAttributeMaxDynamicSharedMemorySize, GEMM_SMEM);
        attr_set = true;
    }

    // 1) CSR build
    zero_int_kernel<<<(NN + 255) / 256, 256>>>(cnt, NN);
    count_edges_kernel<<<(E + 255) / 256, 256>>>(erow, E, cnt);
    scan_kernel<<<1, 1024>>>(cnt, rowptr, cursor);
    fill_csr_kernel<<<(E + 255) / 256, 256>>>(erow, ecol, ew, E, cursor, ccol, cw);

    // 2) splits for support GEMM
    split3_kernel<<<(NN * F_IN + 255) / 256, 256>>>(x, xs, F_IN, 0, NN * F_IN);
    split3T_kernel<<<(F_IN * H + 255) / 256, 256>>>(gcW, gcWs, F_IN, H, F_IN * H);

    // 3) support = x @ gc_W  (HMMA, Kp=1536)
    hmma_gemm_kernel<<<dim3(1, NN / 128), 256, GEMM_SMEM>>>(
        xs, gcWs, nullptr, support, KPX, H);

    // 4) H1 = relu(segment_sum(w * support[col]))
    gather_relu_kernel<<<NN, 256>>>(support, ccol, cw, rowptr, H1);

    // 5) splits for projections
    split3_kernel<<<(NN * H + 255) / 256, 256>>>(H1, H1s, H, 0, NN * H);
    split3_kernel<<<(H * H + 255) / 256, 256>>>(nodeW, nWs, H, 1, H * H);
    split3_kernel<<<(H * H + 255) / 256, 256>>>(neighW, gWs, H, 1, H * H);

    // 6) node_emb / neigh_emb (HMMA, Kp=768)
    hmma_gemm_kernel<<<dim3(1, NN / 128), 256, GEMM_SMEM>>>(
        H1s, nWs, nodeb, node_emb, KP3, H);
    hmma_gemm_kernel<<<dim3(1, NN / 128), 256, GEMM_SMEM>>>(
        H1s, gWs, neighb, neigh_emb, KP3, H);

    // 7) adj = node_emb @ neigh_emb^T (HMMA, Kp=768)
    split_emb_kernel<<<(NN * H) / 256, 256>>>(node_emb, neigh_emb, A2, B2);
    hmma_gemm_kernel<<<dim3(NN / 256, NN / 128), 256, GEMM_SMEM>>>(
        A2, B2, nullptr, adj, KP3, NN);
}